// round 13
// baseline (speedup 1.0000x reference)
#include <cuda_runtime.h>
#include <cuda_fp16.h>

// DAGProp: layered DAG, B=64 identical graphs, 11 levels x 10000 nodes,
// K=16 children per father, edges level-contiguous (dst = repeat(fathers, 16)).
//   leaves:   out = tanh(x)
//   level l:  out[f] = tanh(x[f]*w_r + b_l + (w_l/16)*sum(out[children]))
// One kernel per level. FP16 node-major gather scratch (128 B/row), fp32 math,
// HW tanh.approx. k_level: ONE father per warp, each half-warp covers a
// different child row per LDG.64 (8 LDG.64/warp for 16 children), cross-half
// combine via shfl_xor(16). 10000 warps/level for latency hiding.

#define BB     64        // batch
#define NN     110000    // nodes per graph
#define NPLV   10000     // nodes per level
#define KK     16        // children per father
#define LEVELS 10        // non-leaf levels

// Gather-source scratch (node-major [n][b], fp16). Levels 0..LEVELS-1 used.
__device__ __half g_outH[(size_t)NPLV * LEVELS * BB];

__device__ __forceinline__ float fast_tanh(float v) {
    float r;
    asm("tanh.approx.f32 %0, %1;" : "=f"(r) : "f"(v));
    return r;
}

// ---------------------------------------------------------------------------
// k_pre: leaves only. Read x[:, 0:NPLV] coalesced; write tanh(x) to d_out
// (fp32, batch-major) and to g_outH (fp16, node-major via smem transpose).
// ---------------------------------------------------------------------------
__global__ void k_pre(const float* __restrict__ x, float* __restrict__ out) {
    __shared__ float tile[32][33];
    const int n0 = blockIdx.x * 32;
    const int b0 = blockIdx.y * 32;
    const int tx = threadIdx.x, ty = threadIdx.y;

    int n = n0 + tx;            // coalesced over n
    int b = b0 + ty;
    float v = 0.0f;
    if (n < NPLV) {
        v = tanhf(x[(size_t)b * NN + n]);
        out[(size_t)b * NN + n] = v;
    }
    tile[ty][tx] = v;
    __syncthreads();

    int n2 = n0 + ty;           // coalesced over b
    int b2 = b0 + tx;
    if (n2 < NPLV)
        g_outH[(size_t)n2 * BB + b2] = __float2half_rn(tile[tx][ty]);
}

// ---------------------------------------------------------------------------
// k_level: 4 fathers / 128-thread block, 1 father / warp.
// Lane l: h = l>>4 (child-parity), s = l&15 (owns batches 4s..4s+3, 8 B of a
// 128 B row). Gather j loads child idx[2j+h]: 8 LDG.64 per warp cover all 16
// children. Cross-half combine: shfl_xor(16) on the 4 partial sums.
// ---------------------------------------------------------------------------
__global__ void __launch_bounds__(128, 12) k_level(
    const int* __restrict__ srcidx,   // edge_index row 0 (children)
    const float* __restrict__ x,
    const float* __restrict__ wl,
    const float* __restrict__ bl,
    const float* __restrict__ wr,
    float* __restrict__ out,
    int level)
{
    __shared__ float sm_x[4][68];   // row stride 68 floats (16B-aligned rows)
    __shared__ float sm_o[4][68];

    const int tid = threadIdx.x;
    const int w   = tid >> 5;             // warp 0..3 = father within block
    const int l   = tid & 31;
    const int h   = l >> 4;               // child parity
    const int s   = l & 15;               // 4-batch group
    const int flb = blockIdx.x * 4;       // first father (local) of this block
    const int fl  = flb + w;              // this warp's father (local)

    // --- Child indices: each half-warp loads the father's 16 ints ---
    const int myidx = __ldg(srcidx + ((size_t)(level - 1) * NPLV + fl) * KK + s);

    // --- Stage x for the block's 4 fathers (batch-major reads) ---
    const int fo = tid & 3;
    const int br = tid >> 2;              // 0..31
    const size_t col = (size_t)(level * NPLV + flb + fo);
    const float x0 = x[(size_t)br        * NN + col];
    const float x1 = x[(size_t)(br + 32) * NN + col];

    // --- 8 LDG.64 gathers: half h reads child rows idx[2j+h] ---
    const __half* ob = g_outH + 4 * s;
    uint2 v[8];
    #pragma unroll
    for (int j = 0; j < 8; j++) {
        const int c = __shfl_sync(0xffffffffu, myidx, 2 * j + h, 16);
        v[j] = *reinterpret_cast<const uint2*>(ob + (size_t)c * BB);
    }

    // --- x transpose through smem (overlapped with gathers in flight) ---
    sm_x[fo][br]      = x0;
    sm_x[fo][br + 32] = x1;
    __syncthreads();
    const float4 xv = *reinterpret_cast<const float4*>(&sm_x[w][4 * s]);

    const float Wr = __ldg(wr);
    const float Bl = __ldg(bl);
    const float scale = __ldg(wl) * (1.0f / (float)KK);

    // --- Convert + reduce in fp32 (4 independent chains, 8 children each) ---
    float s0 = 0.f, s1 = 0.f, s2 = 0.f, s3 = 0.f;
    #pragma unroll
    for (int j = 0; j < 8; j++) {
        const __half2 hlo = *reinterpret_cast<const __half2*>(&v[j].x);
        const __half2 hhi = *reinterpret_cast<const __half2*>(&v[j].y);
        const float2 flo = __half22float2(hlo);
        const float2 fhi = __half22float2(hhi);
        s0 += flo.x; s1 += flo.y; s2 += fhi.x; s3 += fhi.y;
    }
    // Cross-half combine: lanes (0,s) and (1,s) hold complementary child sets.
    s0 += __shfl_xor_sync(0xffffffffu, s0, 16);
    s1 += __shfl_xor_sync(0xffffffffu, s1, 16);
    s2 += __shfl_xor_sync(0xffffffffu, s2, 16);
    s3 += __shfl_xor_sync(0xffffffffu, s3, 16);

    float4 o;
    o.x = fast_tanh(fmaf(s0, scale, fmaf(xv.x, Wr, Bl)));
    o.y = fast_tanh(fmaf(s1, scale, fmaf(xv.y, Wr, Bl)));
    o.z = fast_tanh(fmaf(s2, scale, fmaf(xv.z, Wr, Bl)));
    o.w = fast_tanh(fmaf(s3, scale, fmaf(xv.w, Wr, Bl)));

    if (h == 0) {
        if (level < LEVELS) {   // last level is never a gather source
            uint2 oh;
            *reinterpret_cast<__half2*>(&oh.x) = __floats2half2_rn(o.x, o.y);
            *reinterpret_cast<__half2*>(&oh.y) = __floats2half2_rn(o.z, o.w);
            *reinterpret_cast<uint2*>(
                g_outH + (size_t)(level * NPLV + fl) * BB + 4 * s) = oh;
        }
        *reinterpret_cast<float4*>(&sm_o[w][4 * s]) = o;
    }
    __syncthreads();

    // --- Final output [B, N] via smem transpose ---
    out[(size_t)br        * NN + col] = sm_o[fo][br];
    out[(size_t)(br + 32) * NN + col] = sm_o[fo][br + 32];
}

// ---------------------------------------------------------------------------
// Launch (graph-capturable, allocation-free).
// Inputs: x, w_l, b_l, w_r, edge_index, num_levels
// ---------------------------------------------------------------------------
extern "C" void kernel_launch(void* const* d_in, const int* in_sizes, int n_in,
                              void* d_out, int out_size) {
    const float* x  = (const float*)d_in[0];
    const float* wl = (const float*)d_in[1];
    const float* bl = (const float*)d_in[2];
    const float* wr = (const float*)d_in[3];
    const int*   ei = (const int*)d_in[4];   // [2, E]; row 0 = children
    float* out = (float*)d_out;

    dim3 blk(32, 32);
    dim3 grd((NPLV + 31) / 32, BB / 32);
    k_pre<<<grd, blk>>>(x, out);

    const int blocks = NPLV / 4;   // 2500
    for (int l = 1; l <= LEVELS; l++) {
        k_level<<<blocks, 128>>>(ei, x, wl, bl, wr, out, l);
    }
}